// round 16
// baseline (speedup 1.0000x reference)
#include <cuda_runtime.h>
#include <math.h>
#include <stdint.h>

#define NN 50000
#define EE 800000
#define GG 128
#define LL 4
#define TT 4
#define FF 20
#define DD 80
#define EDIM 16
#define AVG_DEG_LOG 2.8332133440562162f
#define EPS_STD 1e-5f
#define EPS_BN  1e-5f

typedef unsigned long long u64;

__device__ __forceinline__ float tf32r(float x) {
    unsigned r;
    asm("cvt.rna.tf32.f32 %0, %1;" : "=r"(r) : "f"(x));
    return __uint_as_float(r);
}

__device__ __forceinline__ u64 bcast2(float x) {
    unsigned xi = __float_as_uint(x);
    u64 r;
    asm("mov.b64 %0, {%1, %1};" : "=l"(r) : "r"(xi));
    return r;
}

__device__ __forceinline__ u64 tf32p(float x) {
    unsigned r;
    asm("cvt.rna.tf32.f32 %0, %1;" : "=r"(r) : "f"(x));
    u64 p;
    asm("mov.b64 %0, {%1, %1};" : "=l"(p) : "r"(r));
    return p;
}

__device__ __forceinline__ u64 ffma2(u64 a, u64 b, u64 c) {
    u64 d;
    asm("fma.rn.f32x2 %0, %1, %2, %3;" : "=l"(d) : "l"(a), "l"(b), "l"(c));
    return d;
}

__device__ __forceinline__ void unpk(float& lo, float& hi, u64 v) {
    unsigned a, b;
    asm("mov.b64 {%0, %1}, %2;" : "=r"(a), "=r"(b) : "l"(v));
    lo = __uint_as_float(a);
    hi = __uint_as_float(b);
}

__device__ __forceinline__ void fma20p(u64* acc, u64 v2, const float* row) {
    const ulonglong2* wr = reinterpret_cast<const ulonglong2*>(row);
#pragma unroll
    for (int i = 0; i < 5; i++) {
        ulonglong2 w = wr[i];
        acc[2 * i]     = ffma2(v2, w.x, acc[2 * i]);
        acc[2 * i + 1] = ffma2(v2, w.y, acc[2 * i + 1]);
    }
}

__device__ __forceinline__ void fma20p2(u64* a0, u64* a1, u64 v0, u64 v1, const float* row) {
    const ulonglong2* wr = reinterpret_cast<const ulonglong2*>(row);
#pragma unroll
    for (int i = 0; i < 5; i++) {
        ulonglong2 w = wr[i];
        a0[2 * i]     = ffma2(v0, w.x, a0[2 * i]);
        a0[2 * i + 1] = ffma2(v0, w.y, a0[2 * i + 1]);
        a1[2 * i]     = ffma2(v1, w.x, a1[2 * i]);
        a1[2 * i + 1] = ffma2(v1, w.y, a1[2 * i + 1]);
    }
}

// ---------------- scratch ----------------
__device__ float d_h[NN * DD];
__device__ float d_m[(size_t)EE * DD];
__device__ float d_A[NN * DD];
__device__ float d_B[NN * DD];
__device__ float d_agg[NN * 4 * DD];
__device__ float d_pre[NN * DD];
__device__ float d_lin[NN * DD];
__device__ int   d_degcur[2 * NN];
__device__ int   d_rowoff[NN + 1];
__device__ int   d_src_s[EE];
__device__ int   d_dst_s[EE];
__device__ float d_eatt_s[(size_t)EE * EDIM];
__device__ float d_C[TT * EDIM * FF];      // composed ea->hidden map per tower
__device__ float d_dv[TT * FF];            // composed bias W1e@eb per tower
__device__ float d_s1[NN], d_s2[NN], d_invdeg[NN];
__device__ float d_bnsum[DD], d_bnsq[DD], d_scale[DD], d_shift[DD];
__device__ float d_gsum[GG * DD], d_gcnt[GG];

// ---------------- prep (fused) ----------------
__global__ void k_count_init(const int* __restrict__ ei, const int* __restrict__ x,
                             const float* __restrict__ aemb) {
    int i = blockIdx.x * blockDim.x + threadIdx.x;
    if (i < EE) atomicAdd(&d_degcur[ei[EE + i]], 1);
    if (i < NN * 20) {
        int n = i / 20, c = i % 20;
        float4 acc = make_float4(0.f, 0.f, 0.f, 0.f);
#pragma unroll
        for (int p = 0; p < 9; p++) {
            int a = x[n * 9 + p];
            const float4* src = reinterpret_cast<const float4*>(aemb + (p * 16 + a) * DD);
            float4 v = src[c];
            acc.x += v.x; acc.y += v.y; acc.z += v.z; acc.w += v.w;
        }
        reinterpret_cast<float4*>(d_h + n * DD)[c] = acc;
    }
}

__global__ void k_scan() {
    __shared__ int part[1024];
    int tid = threadIdx.x;
    const int CH = (NN + 1023) / 1024;
    int base = tid * CH;
    int s = 0;
    for (int i = 0; i < CH; i++) {
        int idx = base + i;
        if (idx < NN) s += d_degcur[idx];
    }
    part[tid] = s;
    __syncthreads();
    for (int off = 1; off < 1024; off <<= 1) {
        int v = (tid >= off) ? part[tid - off] : 0;
        __syncthreads();
        part[tid] += v;
        __syncthreads();
    }
    int run = (tid == 0) ? 0 : part[tid - 1];
    for (int i = 0; i < CH; i++) {
        int idx = base + i;
        if (idx < NN) {
            d_rowoff[idx] = run;
            int dr = d_degcur[idx];
            run += dr;
            float deg = (dr > 0) ? (float)dr : 1.0f;
            d_invdeg[idx] = 1.0f / deg;
            float logd = logf(deg + 1.0f);
            d_s1[idx] = logd / AVG_DEG_LOG;
            d_s2[idx] = AVG_DEG_LOG / logd;
        }
    }
    if (tid == 0) d_rowoff[NN] = part[1023];
}

__global__ void k_fillreorder(const int* __restrict__ ei, const float* __restrict__ eattr) {
    int e = blockIdx.x * blockDim.x + threadIdx.x;
    if (e >= EE) return;
    int dd = ei[EE + e];
    int pos = atomicAdd(&d_degcur[NN + dd], 1);
    int slot = d_rowoff[dd] + pos;
    d_src_s[slot] = ei[e];
    d_dst_s[slot] = dd;
    const float4* src = reinterpret_cast<const float4*>(eattr + (size_t)e * EDIM);
    float4* dst = reinterpret_cast<float4*>(d_eatt_s + (size_t)slot * EDIM);
#pragma unroll
    for (int j = 0; j < 4; j++) dst[j] = src[j];
}

// ---------------- per-layer: compose C = W1e @ Ew, dv = W1e @ eb ----------------
__global__ void k_compose(const float* __restrict__ ew, const float* __restrict__ ebias,
                          const float* __restrict__ w1) {
    int tid = threadIdx.x;
    if (tid < TT * EDIM) {
        int t = tid / EDIM, k = tid % EDIM;
        float acc[FF];
#pragma unroll
        for (int o = 0; o < FF; o++) acc[o] = 0.f;
        for (int o = 0; o < FF; o++) {
            float ewv = tf32r(ew[k * FF + o]);
            const float* wrow = w1 + t * 3 * FF * FF + 2 * FF * FF + o * FF;
#pragma unroll
            for (int o2 = 0; o2 < FF; o2++) acc[o2] += ewv * tf32r(wrow[o2]);
        }
#pragma unroll
        for (int o2 = 0; o2 < FF; o2++) d_C[t * EDIM * FF + k * FF + o2] = acc[o2];
    }
    if (tid < TT * FF) {
        int t = tid / FF, o2 = tid % FF;
        float a = 0.f;
        for (int o = 0; o < FF; o++)
            a += ebias[o] * tf32r(w1[t * 3 * FF * FF + 2 * FF * FF + o * FF + o2]);
        d_dv[tid] = a;
    }
}

// ---------------- node precompute: A = W1d@h, B = W1s@h ----------------
__global__ void __launch_bounds__(256) k_nodepre(const float* __restrict__ w1) {
    __shared__ __align__(16) float sWd[TT * FF * FF];
    __shared__ __align__(16) float sWs[TT * FF * FF];
    int tid = threadIdx.x;
    for (int i = tid; i < TT * FF * FF; i += 256) {
        int t = i / (FF * FF), r = i % (FF * FF);
        sWd[i] = tf32r(w1[t * 3 * FF * FF + r]);
        sWs[i] = tf32r(w1[t * 3 * FF * FF + FF * FF + r]);
    }
    __syncthreads();
    int n = blockIdx.x * 256 + tid;
    if (n >= NN) return;
    const float4* ph = reinterpret_cast<const float4*>(d_h + n * DD);
    for (int t = 0; t < TT; t++) {
        u64 aA[10], aB[10];
#pragma unroll
        for (int i = 0; i < 10; i++) { aA[i] = 0ull; aB[i] = 0ull; }
#pragma unroll
        for (int i4 = 0; i4 < 5; i4++) {
            float4 v = ph[t * 5 + i4];
            u64 px = tf32p(v.x), py = tf32p(v.y), pz = tf32p(v.z), pw = tf32p(v.w);
            fma20p(aA, px, sWd + t * 400 + (i4 * 4 + 0) * FF);
            fma20p(aA, py, sWd + t * 400 + (i4 * 4 + 1) * FF);
            fma20p(aA, pz, sWd + t * 400 + (i4 * 4 + 2) * FF);
            fma20p(aA, pw, sWd + t * 400 + (i4 * 4 + 3) * FF);
            fma20p(aB, px, sWs + t * 400 + (i4 * 4 + 0) * FF);
            fma20p(aB, py, sWs + t * 400 + (i4 * 4 + 1) * FF);
            fma20p(aB, pz, sWs + t * 400 + (i4 * 4 + 2) * FF);
            fma20p(aB, pw, sWs + t * 400 + (i4 * 4 + 3) * FF);
        }
        float4* pa = reinterpret_cast<float4*>(d_A + n * DD + t * FF);
        float4* pb = reinterpret_cast<float4*>(d_B + n * DD + t * FF);
#pragma unroll
        for (int i = 0; i < 5; i++) {
            float l0, h0, l1, h1;
            unpk(l0, h0, aA[2 * i]);
            unpk(l1, h1, aA[2 * i + 1]);
            pa[i] = make_float4(l0, h0, l1, h1);
            unpk(l0, h0, aB[2 * i]);
            unpk(l1, h1, aB[2 * i + 1]);
            pb[i] = make_float4(l0, h0, l1, h1);
        }
    }
}

// ---------------- edge MLP (composed ea path + dual-edge weight sharing) ----------------
// smem floats: sC[1280] sW2[1600] sB1c[80] sB2[80] sAT[32*128]
#define EDGE_SMEM_FLOATS (1280 + 1600 + 80 + 80 + 32 * 128)

__global__ void __launch_bounds__(128) k_edge(
                       const float* __restrict__ b1, const float* __restrict__ w2,
                       const float* __restrict__ b2) {
    extern __shared__ float sm[];
    float* sC   = sm;                  // 1280: [t][k][o2]
    float* sW2  = sm + 1280;           // 1600
    float* sB1c = sm + 2880;           // 80: b1 + dv
    float* sB2  = sm + 2960;           // 80
    float* sAT  = sm + 3040;           // [32][128]: tf32(attr), 2 edges
    int tid = threadIdx.x;
    for (int i = tid; i < TT * EDIM * FF; i += 128) sC[i] = tf32r(d_C[i]);
    for (int i = tid; i < TT * FF * FF; i += 128) sW2[i] = tf32r(w2[i]);
    for (int i = tid; i < TT * FF; i += 128) { sB1c[i] = b1[i] + d_dv[i]; sB2[i] = b2[i]; }
    __syncthreads();

    int e0 = blockIdx.x * 256 + tid;   // EE = 3125*256 exactly
    int e1 = e0 + 128;
    int s0 = d_src_s[e0], dd0 = d_dst_s[e0];
    int s1i = d_src_s[e1], dd1 = d_dst_s[e1];

    // stage tf32(attr) into per-thread smem columns (no barrier: own column only)
    {
        const float4* r0 = reinterpret_cast<const float4*>(d_eatt_s + (size_t)e0 * EDIM);
        const float4* r1 = reinterpret_cast<const float4*>(d_eatt_s + (size_t)e1 * EDIM);
#pragma unroll
        for (int j4 = 0; j4 < 4; j4++) {
            float4 v0 = r0[j4], v1 = r1[j4];
            sAT[(j4 * 4 + 0) * 128 + tid] = tf32r(v0.x);
            sAT[(j4 * 4 + 1) * 128 + tid] = tf32r(v0.y);
            sAT[(j4 * 4 + 2) * 128 + tid] = tf32r(v0.z);
            sAT[(j4 * 4 + 3) * 128 + tid] = tf32r(v0.w);
            sAT[(EDIM + j4 * 4 + 0) * 128 + tid] = tf32r(v1.x);
            sAT[(EDIM + j4 * 4 + 1) * 128 + tid] = tf32r(v1.y);
            sAT[(EDIM + j4 * 4 + 2) * 128 + tid] = tf32r(v1.z);
            sAT[(EDIM + j4 * 4 + 3) * 128 + tid] = tf32r(v1.w);
        }
    }

    float* m0 = d_m + (size_t)e0 * DD;
    float* m1 = d_m + (size_t)e1 * DD;
    for (int t = 0; t < TT; t++) {
        // pe = C_t @ attr (16 shared weight rows)
        u64 pe0[10], pe1[10];
#pragma unroll
        for (int i = 0; i < 10; i++) { pe0[i] = 0ull; pe1[i] = 0ull; }
#pragma unroll
        for (int k = 0; k < EDIM; k++) {
            u64 b0 = bcast2(sAT[k * 128 + tid]);
            u64 b1v = bcast2(sAT[(EDIM + k) * 128 + tid]);
            fma20p2(pe0, pe1, b0, b1v, sC + t * EDIM * FF + k * FF);
        }

        // hid = A[dd] + B[s] + pe + (b1+dv) -> relu -> tf32
        const float4* pa0 = reinterpret_cast<const float4*>(d_A + dd0 * DD + t * FF);
        const float4* pb0 = reinterpret_cast<const float4*>(d_B + s0 * DD + t * FF);
        const float4* pa1 = reinterpret_cast<const float4*>(d_A + dd1 * DD + t * FF);
        const float4* pb1 = reinterpret_cast<const float4*>(d_B + s1i * DD + t * FF);
        float hs0[FF], hs1[FF];
#pragma unroll
        for (int i = 0; i < 5; i++) {
            float4 av = pa0[i];
            float4 bv = pb0[i];
            float lo, hi;
            unpk(lo, hi, pe0[2 * i]);
            hs0[4 * i + 0] = tf32r(fmaxf(av.x + bv.x + lo + sB1c[t * FF + 4 * i + 0], 0.f));
            hs0[4 * i + 1] = tf32r(fmaxf(av.y + bv.y + hi + sB1c[t * FF + 4 * i + 1], 0.f));
            unpk(lo, hi, pe0[2 * i + 1]);
            hs0[4 * i + 2] = tf32r(fmaxf(av.z + bv.z + lo + sB1c[t * FF + 4 * i + 2], 0.f));
            hs0[4 * i + 3] = tf32r(fmaxf(av.w + bv.w + hi + sB1c[t * FF + 4 * i + 3], 0.f));
        }
#pragma unroll
        for (int i = 0; i < 5; i++) {
            float4 av = pa1[i];
            float4 bv = pb1[i];
            float lo, hi;
            unpk(lo, hi, pe1[2 * i]);
            hs1[4 * i + 0] = tf32r(fmaxf(av.x + bv.x + lo + sB1c[t * FF + 4 * i + 0], 0.f));
            hs1[4 * i + 1] = tf32r(fmaxf(av.y + bv.y + hi + sB1c[t * FF + 4 * i + 1], 0.f));
            unpk(lo, hi, pe1[2 * i + 1]);
            hs1[4 * i + 2] = tf32r(fmaxf(av.z + bv.z + lo + sB1c[t * FF + 4 * i + 2], 0.f));
            hs1[4 * i + 3] = tf32r(fmaxf(av.w + bv.w + hi + sB1c[t * FF + 4 * i + 3], 0.f));
        }

        // out = W2 @ hs + b2 (weight rows shared), direct streaming stores
        u64 o0[10], o1[10];
#pragma unroll
        for (int i = 0; i < 10; i++) { o0[i] = 0ull; o1[i] = 0ull; }
#pragma unroll
        for (int i = 0; i < FF; i++)
            fma20p2(o0, o1, bcast2(hs0[i]), bcast2(hs1[i]), sW2 + t * 400 + i * FF);
#pragma unroll
        for (int i = 0; i < 5; i++) {
            float l0, g0, l1, g1;
            unpk(l0, g0, o0[2 * i]);
            unpk(l1, g1, o0[2 * i + 1]);
            __stcs(reinterpret_cast<float4*>(m0 + t * FF) + i,
                   make_float4(l0 + sB2[t * FF + 4 * i], g0 + sB2[t * FF + 4 * i + 1],
                               l1 + sB2[t * FF + 4 * i + 2], g1 + sB2[t * FF + 4 * i + 3]));
            unpk(l0, g0, o1[2 * i]);
            unpk(l1, g1, o1[2 * i + 1]);
            __stcs(reinterpret_cast<float4*>(m1 + t * FF) + i,
                   make_float4(l0 + sB2[t * FF + 4 * i], g0 + sB2[t * FF + 4 * i + 1],
                               l1 + sB2[t * FF + 4 * i + 2], g1 + sB2[t * FF + 4 * i + 3]));
        }
    }
}

// ---------------- aggregation ----------------
__device__ __forceinline__ void agg_write(float* base, int d, float s, float q,
                                          float mn, float mx, float inv, bool he) {
    float mean = s * inv;
    float msq = q * inv;
    float sd = sqrtf(fmaxf(msq - mean * mean, 0.f) + EPS_STD);
    base[0 * DD + d] = mean;
    base[1 * DD + d] = he ? mn : 0.f;
    base[2 * DD + d] = he ? mx : 0.f;
    base[3 * DD + d] = sd;
}

__global__ void k_agg() {
    int warp = (blockIdx.x * blockDim.x + threadIdx.x) >> 5;
    int lane = threadIdx.x & 31;
    if (warp >= NN) return;
    int n = warp;
    int beg = d_rowoff[n], end = d_rowoff[n + 1];
    float s0 = 0, s1 = 0, s2 = 0, q0 = 0, q1 = 0, q2 = 0;
    float mn0 = INFINITY, mn1 = INFINITY, mn2 = INFINITY;
    float mx0 = -INFINITY, mx1 = -INFINITY, mx2 = -INFINITY;
    int i = beg;
    for (; i + 1 < end; i += 2) {
        const float* r0 = d_m + (size_t)i * DD;
        const float* r1 = r0 + DD;
        float a0 = __ldcs(r0 + lane);
        float a1 = __ldcs(r0 + 32 + lane);
        float b0 = __ldcs(r1 + lane);
        float b1 = __ldcs(r1 + 32 + lane);
        float a2 = 0.f, b2 = 0.f;
        if (lane < 16) { a2 = __ldcs(r0 + 64 + lane); b2 = __ldcs(r1 + 64 + lane); }
        s0 += a0; q0 += a0 * a0; mn0 = fminf(mn0, a0); mx0 = fmaxf(mx0, a0);
        s1 += a1; q1 += a1 * a1; mn1 = fminf(mn1, a1); mx1 = fmaxf(mx1, a1);
        s0 += b0; q0 += b0 * b0; mn0 = fminf(mn0, b0); mx0 = fmaxf(mx0, b0);
        s1 += b1; q1 += b1 * b1; mn1 = fminf(mn1, b1); mx1 = fmaxf(mx1, b1);
        if (lane < 16) {
            s2 += a2; q2 += a2 * a2; mn2 = fminf(mn2, a2); mx2 = fmaxf(mx2, a2);
            s2 += b2; q2 += b2 * b2; mn2 = fminf(mn2, b2); mx2 = fmaxf(mx2, b2);
        }
    }
    if (i < end) {
        const float* r0 = d_m + (size_t)i * DD;
        float a0 = __ldcs(r0 + lane);
        float a1 = __ldcs(r0 + 32 + lane);
        s0 += a0; q0 += a0 * a0; mn0 = fminf(mn0, a0); mx0 = fmaxf(mx0, a0);
        s1 += a1; q1 += a1 * a1; mn1 = fminf(mn1, a1); mx1 = fmaxf(mx1, a1);
        if (lane < 16) {
            float a2 = __ldcs(r0 + 64 + lane);
            s2 += a2; q2 += a2 * a2; mn2 = fminf(mn2, a2); mx2 = fmaxf(mx2, a2);
        }
    }
    float inv = d_invdeg[n];
    bool he = (end > beg);
    float* base = d_agg + n * 4 * DD;
    agg_write(base, lane, s0, q0, mn0, mx0, inv, he);
    agg_write(base, 32 + lane, s1, q1, mn1, mx1, inv, he);
    if (lane < 16) agg_write(base, 64 + lane, s2, q2, mn2, mx2, inv, he);
}

// ---------------- post MLP (tower-split) ----------------
__global__ void __launch_bounds__(256) k_post(const float* __restrict__ w1,
                                              const float* __restrict__ b1,
                                              const float* __restrict__ w2,
                                              const float* __restrict__ b2) {
    __shared__ __align__(16) float sW1[13 * FF * FF];
    __shared__ __align__(16) float sW2[FF * FF];
    __shared__ float sB1[FF];
    __shared__ float sB2[FF];
    int tid = threadIdx.x;
    int t = blockIdx.y;
    const float* w1t = w1 + t * 13 * FF * FF;
    const float* w2t = w2 + t * FF * FF;
    for (int i = tid; i < 13 * FF * FF; i += 256) sW1[i] = tf32r(w1t[i]);
    for (int i = tid; i < FF * FF; i += 256) sW2[i] = tf32r(w2t[i]);
    if (tid < FF) { sB1[tid] = b1[t * FF + tid]; sB2[tid] = b2[t * FF + tid]; }
    __syncthreads();

    int n = blockIdx.x * 256 + tid;
    if (n >= NN) return;
    float s1v = d_s1[n], s2v = d_s2[n];

    u64 hid[10];
#pragma unroll
    for (int i = 0; i < 10; i++) hid[i] = 0ull;
    const float4* px = reinterpret_cast<const float4*>(d_h + n * DD + t * FF);
#pragma unroll
    for (int i4 = 0; i4 < 5; i4++) {
        float4 v = px[i4];
        fma20p(hid, tf32p(v.x), sW1 + (i4 * 4 + 0) * FF);
        fma20p(hid, tf32p(v.y), sW1 + (i4 * 4 + 1) * FF);
        fma20p(hid, tf32p(v.z), sW1 + (i4 * 4 + 2) * FF);
        fma20p(hid, tf32p(v.w), sW1 + (i4 * 4 + 3) * FF);
    }
    for (int k = 0; k < 4; k++) {
        const float4* pa = reinterpret_cast<const float4*>(d_agg + n * 4 * DD + k * DD + t * FF);
#pragma unroll
        for (int f4 = 0; f4 < 5; f4++) {
            float4 v = pa[f4];
#pragma unroll
            for (int c = 0; c < 4; c++) {
                float a = (c == 0) ? v.x : (c == 1) ? v.y : (c == 2) ? v.z : v.w;
                int j = k * FF + f4 * 4 + c;
                fma20p(hid, tf32p(a), sW1 + (FF + j) * FF);
                fma20p(hid, tf32p(a * s1v), sW1 + (5 * FF + j) * FF);
                fma20p(hid, tf32p(a * s2v), sW1 + (9 * FF + j) * FF);
            }
        }
    }
    float hs[FF];
#pragma unroll
    for (int i = 0; i < 10; i++) {
        float lo, hi;
        unpk(lo, hi, hid[i]);
        hs[2 * i]     = tf32r(fmaxf(lo + sB1[2 * i], 0.f));
        hs[2 * i + 1] = tf32r(fmaxf(hi + sB1[2 * i + 1], 0.f));
    }
    u64 ov[10];
#pragma unroll
    for (int i = 0; i < 10; i++) ov[i] = 0ull;
#pragma unroll
    for (int i = 0; i < FF; i++) fma20p(ov, bcast2(hs[i]), sW2 + i * FF);
    float4* po = reinterpret_cast<float4*>(d_pre + n * DD + t * FF);
#pragma unroll
    for (int i = 0; i < 5; i++) {
        float l0, h0, l1, h1;
        unpk(l0, h0, ov[2 * i]);
        unpk(l1, h1, ov[2 * i + 1]);
        po[i] = make_float4(l0 + sB2[4 * i], h0 + sB2[4 * i + 1],
                            l1 + sB2[4 * i + 2], h1 + sB2[4 * i + 3]);
    }
}

// ---------------- lin ----------------
__global__ void k_lin(const float* __restrict__ lw, const float* __restrict__ lb) {
    __shared__ __align__(16) float sW[DD * DD];
    __shared__ __align__(16) float sLb[DD];
    int tid = threadIdx.x, bd = blockDim.x;
    for (int i = tid; i < DD * DD; i += bd) sW[i] = tf32r(lw[i]);
    for (int i = tid; i < DD; i += bd) sLb[i] = lb[i];
    __syncthreads();
    int n = blockIdx.x * bd + tid;
    if (n >= NN) return;
    const float4* pr = reinterpret_cast<const float4*>(d_pre + n * DD);
    u64 acc[40];
#pragma unroll
    for (int i = 0; i < 40; i++) acc[i] = 0ull;
#pragma unroll
    for (int k4 = 0; k4 < 20; k4++) {
        float4 v = pr[k4];
#pragma unroll
        for (int c = 0; c < 4; c++) {
            float a = (c == 0) ? v.x : (c == 1) ? v.y : (c == 2) ? v.z : v.w;
            u64 ap = tf32p(a);
            const float* wrow = sW + (k4 * 4 + c) * DD;
            fma20p(acc,      ap, wrow);
            fma20p(acc + 10, ap, wrow + 20);
            fma20p(acc + 20, ap, wrow + 40);
            fma20p(acc + 30, ap, wrow + 60);
        }
    }
    float4* po = reinterpret_cast<float4*>(d_lin + n * DD);
#pragma unroll
    for (int i = 0; i < 20; i++) {
        float l0, h0, l1, h1;
        unpk(l0, h0, acc[2 * i]);
        unpk(l1, h1, acc[2 * i + 1]);
        po[i] = make_float4(l0 + sLb[4 * i], h0 + sLb[4 * i + 1],
                            l1 + sLb[4 * i + 2], h1 + sLb[4 * i + 3]);
    }
}

// ---------------- batch norm ----------------
__global__ void k_zero_bn() {
    int i = threadIdx.x;
    if (i < DD) { d_bnsum[i] = 0.f; d_bnsq[i] = 0.f; }
}

__global__ void k_bn_stats() {
    int gid = blockIdx.x * blockDim.x + threadIdx.x;
    int f = gid % DD;
    float s = 0.f, q = 0.f;
    for (int i = gid; i < NN * DD; i += 40960) {
        float v = d_lin[i];
        s += v;
        q += v * v;
    }
    atomicAdd(&d_bnsum[f], s);
    atomicAdd(&d_bnsq[f], q);
}

__global__ void k_bn_final(const float* __restrict__ g, const float* __restrict__ b) {
    int i = threadIdx.x;
    if (i >= DD) return;
    float mu = d_bnsum[i] / (float)NN;
    float var = fmaxf(d_bnsq[i] / (float)NN - mu * mu, 0.f);
    float sc = g[i] * rsqrtf(var + EPS_BN);
    d_scale[i] = sc;
    d_shift[i] = b[i] - mu * sc;
}

__global__ void k_bn_apply() {
    int i = blockIdx.x * blockDim.x + threadIdx.x;
    if (i >= NN * DD) return;
    int d = i % DD;
    float v = d_lin[i] * d_scale[d] + d_shift[d];
    d_h[i] = fmaxf(v, 0.f) + d_h[i];
}

// ---------------- readout ----------------
__global__ void k_zero_pool() {
    int i = blockIdx.x * blockDim.x + threadIdx.x;
    if (i < GG * DD) d_gsum[i] = 0.f;
    if (i < GG) d_gcnt[i] = 0.f;
}

__global__ void k_pool(const int* __restrict__ batch) {
    int i = blockIdx.x * blockDim.x + threadIdx.x;
    if (i >= NN * DD) return;
    int n = i / DD, d = i % DD;
    int b = batch[n];
    atomicAdd(&d_gsum[b * DD + d], d_h[i]);
    if (d == 0) atomicAdd(&d_gcnt[b], 1.f);
}

__global__ void k_mlp(const float* __restrict__ w1, const float* __restrict__ b1,
                      const float* __restrict__ w2, const float* __restrict__ b2,
                      const float* __restrict__ w3, const float* __restrict__ b3,
                      float* __restrict__ out) {
    __shared__ float sw1[DD * 40];
    __shared__ float sb1[40];
    __shared__ float sw2[40 * 20];
    __shared__ float sb2[20];
    __shared__ float sw3[20];
    __shared__ float sb3;
    int tid = threadIdx.x;
    for (int i = tid; i < DD * 40; i += blockDim.x) sw1[i] = tf32r(w1[i]);
    for (int i = tid; i < 40 * 20; i += blockDim.x) sw2[i] = tf32r(w2[i]);
    if (tid < 40) sb1[tid] = b1[tid];
    if (tid < 20) { sb2[tid] = b2[tid]; sw3[tid] = tf32r(w3[tid]); }
    if (tid == 0) sb3 = b3[0];
    __syncthreads();

    int g = tid;
    if (g >= GG) return;
    float inv = 1.0f / fmaxf(d_gcnt[g], 1.0f);
    float gin[DD];
#pragma unroll
    for (int i = 0; i < DD; i++) gin[i] = tf32r(d_gsum[g * DD + i] * inv);
    float h1[40];
#pragma unroll
    for (int o = 0; o < 40; o++) h1[o] = 0.f;
#pragma unroll
    for (int i = 0; i < DD; i++) {
        float v = gin[i];
#pragma unroll
        for (int o = 0; o < 40; o++) h1[o] += v * sw1[i * 40 + o];
    }
#pragma unroll
    for (int o = 0; o < 40; o++) h1[o] = tf32r(fmaxf(h1[o] + sb1[o], 0.f));
    float h2[20];
#pragma unroll
    for (int o = 0; o < 20; o++) h2[o] = 0.f;
#pragma unroll
    for (int i = 0; i < 40; i++) {
        float v = h1[i];
#pragma unroll
        for (int o = 0; o < 20; o++) h2[o] += v * sw2[i * 20 + o];
    }
    float acc = 0.f;
#pragma unroll
    for (int i = 0; i < 20; i++) acc += tf32r(fmaxf(h2[i] + sb2[i], 0.f)) * sw3[i];
    out[g] = acc + sb3;
}

// ---------------- host launcher ----------------
extern "C" void kernel_launch(void* const* d_in, const int* in_sizes, int n_in,
                              void* d_out, int out_size) {
    (void)in_sizes; (void)n_in; (void)out_size;
    const int* x          = (const int*)d_in[0];
    const int* ei         = (const int*)d_in[1];
    const int* batch      = (const int*)d_in[2];
    const float* eattr    = (const float*)d_in[3];
    const float* aemb     = (const float*)d_in[4];
    const float* edge_w   = (const float*)d_in[5];
    const float* edge_b   = (const float*)d_in[6];
    const float* pre_w1   = (const float*)d_in[7];
    const float* pre_b1   = (const float*)d_in[8];
    const float* pre_w2   = (const float*)d_in[9];
    const float* pre_b2   = (const float*)d_in[10];
    const float* post_w1  = (const float*)d_in[11];
    const float* post_b1  = (const float*)d_in[12];
    const float* post_w2  = (const float*)d_in[13];
    const float* post_b2  = (const float*)d_in[14];
    const float* lin_w    = (const float*)d_in[15];
    const float* lin_b    = (const float*)d_in[16];
    const float* bn_g     = (const float*)d_in[17];
    const float* bn_b     = (const float*)d_in[18];
    const float* mlp_w1   = (const float*)d_in[19];
    const float* mlp_b1   = (const float*)d_in[20];
    const float* mlp_w2   = (const float*)d_in[21];
    const float* mlp_b2   = (const float*)d_in[22];
    const float* mlp_w3   = (const float*)d_in[23];
    const float* mlp_b3   = (const float*)d_in[24];
    float* out = (float*)d_out;

    const int EDGE_SMEM = EDGE_SMEM_FLOATS * 4;   // ~28.3 KB
    cudaFuncSetAttribute(k_edge, cudaFuncAttributeMaxDynamicSharedMemorySize, EDGE_SMEM);

    void* p_degcur = nullptr;
    cudaGetSymbolAddress(&p_degcur, d_degcur);
    cudaMemsetAsync(p_degcur, 0, 2 * NN * sizeof(int), 0);

    k_count_init<<<(NN * 20 + 255) / 256, 256>>>(ei, x, aemb);
    k_scan<<<1, 1024>>>();
    k_fillreorder<<<(EE + 255) / 256, 256>>>(ei, eattr);

    for (int l = 0; l < LL; l++) {
        k_compose<<<1, 128>>>(edge_w + l * EDIM * FF, edge_b + l * FF,
                              pre_w1 + l * TT * 3 * FF * FF);
        k_nodepre<<<(NN + 255) / 256, 256>>>(pre_w1 + l * TT * 3 * FF * FF);
        k_edge<<<EE / 256, 128, EDGE_SMEM>>>(
            pre_b1 + l * TT * FF,
            pre_w2 + l * TT * FF * FF, pre_b2 + l * TT * FF);
        k_agg<<<(NN * 32 + 255) / 256, 256>>>();
        k_post<<<dim3((NN + 255) / 256, TT), 256>>>(
            post_w1 + l * TT * 13 * FF * FF, post_b1 + l * TT * FF,
            post_w2 + l * TT * FF * FF, post_b2 + l * TT * FF);
        k_lin<<<(NN + 255) / 256, 256>>>(lin_w + l * DD * DD, lin_b + l * DD);
        k_zero_bn<<<1, 128>>>();
        k_bn_stats<<<128, 320>>>();
        k_bn_final<<<1, 80>>>(bn_g + l * DD, bn_b + l * DD);
        k_bn_apply<<<(NN * DD + 255) / 256, 256>>>();
    }

    k_zero_pool<<<(GG * DD + 255) / 256, 256>>>();
    k_pool<<<(NN * DD + 255) / 256, 256>>>(batch);
    k_mlp<<<1, 128>>>(mlp_w1, mlp_b1, mlp_w2, mlp_b2, mlp_w3, mlp_b3, out);
}

// round 17
// speedup vs baseline: 1.0173x; 1.0173x over previous
#include <cuda_runtime.h>
#include <math.h>
#include <stdint.h>

#define NN 50000
#define EE 800000
#define GG 128
#define LL 4
#define TT 4
#define FF 20
#define DD 80
#define EDIM 16
#define AVG_DEG_LOG 2.8332133440562162f
#define EPS_STD 1e-5f
#define EPS_BN  1e-5f

typedef unsigned long long u64;

__device__ __forceinline__ float tf32r(float x) {
    unsigned r;
    asm("cvt.rna.tf32.f32 %0, %1;" : "=r"(r) : "f"(x));
    return __uint_as_float(r);
}

__device__ __forceinline__ u64 bcast2(float x) {
    unsigned xi = __float_as_uint(x);
    u64 r;
    asm("mov.b64 %0, {%1, %1};" : "=l"(r) : "r"(xi));
    return r;
}

__device__ __forceinline__ u64 tf32p(float x) {
    unsigned r;
    asm("cvt.rna.tf32.f32 %0, %1;" : "=r"(r) : "f"(x));
    u64 p;
    asm("mov.b64 %0, {%1, %1};" : "=l"(p) : "r"(r));
    return p;
}

__device__ __forceinline__ u64 ffma2(u64 a, u64 b, u64 c) {
    u64 d;
    asm("fma.rn.f32x2 %0, %1, %2, %3;" : "=l"(d) : "l"(a), "l"(b), "l"(c));
    return d;
}

__device__ __forceinline__ void unpk(float& lo, float& hi, u64 v) {
    unsigned a, b;
    asm("mov.b64 {%0, %1}, %2;" : "=r"(a), "=r"(b) : "l"(v));
    lo = __uint_as_float(a);
    hi = __uint_as_float(b);
}

__device__ __forceinline__ void fma20p(u64* acc, u64 v2, const float* row) {
    const ulonglong2* wr = reinterpret_cast<const ulonglong2*>(row);
#pragma unroll
    for (int i = 0; i < 5; i++) {
        ulonglong2 w = wr[i];
        acc[2 * i]     = ffma2(v2, w.x, acc[2 * i]);
        acc[2 * i + 1] = ffma2(v2, w.y, acc[2 * i + 1]);
    }
}

__device__ __forceinline__ void fma20p2(u64* a0, u64* a1, u64 v0, u64 v1, const float* row) {
    const ulonglong2* wr = reinterpret_cast<const ulonglong2*>(row);
#pragma unroll
    for (int i = 0; i < 5; i++) {
        ulonglong2 w = wr[i];
        a0[2 * i]     = ffma2(v0, w.x, a0[2 * i]);
        a0[2 * i + 1] = ffma2(v0, w.y, a0[2 * i + 1]);
        a1[2 * i]     = ffma2(v1, w.x, a1[2 * i]);
        a1[2 * i + 1] = ffma2(v1, w.y, a1[2 * i + 1]);
    }
}

// ---------------- scratch ----------------
__device__ float d_h[NN * DD];
__device__ float d_m[(size_t)EE * DD];
__device__ float d_A[NN * DD];
__device__ float d_B[NN * DD];
__device__ float d_agg[NN * 4 * DD];
__device__ float d_pre[NN * DD];
__device__ float d_lin[NN * DD];
__device__ int   d_degcur[2 * NN];
__device__ int   d_rowoff[NN + 1];
__device__ int   d_src_s[EE];
__device__ int   d_dst_s[EE];
__device__ float d_eatt_s[(size_t)EE * EDIM];
__device__ float d_C[LL * TT * EDIM * FF];   // composed ea->hidden map, ALL layers
__device__ float d_dv[LL * TT * FF];         // composed bias, ALL layers
__device__ float d_s1[NN], d_s2[NN], d_invdeg[NN];
__device__ float d_bnsum[DD], d_bnsq[DD], d_scale[DD], d_shift[DD];
__device__ float d_gsum[GG * DD], d_gcnt[GG];

// ---------------- prep (fused) ----------------
__global__ void k_count_init(const int* __restrict__ ei, const int* __restrict__ x,
                             const float* __restrict__ aemb) {
    int i = blockIdx.x * blockDim.x + threadIdx.x;
    if (i < EE) atomicAdd(&d_degcur[ei[EE + i]], 1);
    if (i < NN * 20) {
        int n = i / 20, c = i % 20;
        float4 acc = make_float4(0.f, 0.f, 0.f, 0.f);
#pragma unroll
        for (int p = 0; p < 9; p++) {
            int a = x[n * 9 + p];
            const float4* src = reinterpret_cast<const float4*>(aemb + (p * 16 + a) * DD);
            float4 v = src[c];
            acc.x += v.x; acc.y += v.y; acc.z += v.z; acc.w += v.w;
        }
        reinterpret_cast<float4*>(d_h + n * DD)[c] = acc;
    }
}

__global__ void k_scan() {
    __shared__ int part[1024];
    int tid = threadIdx.x;
    const int CH = (NN + 1023) / 1024;
    int base = tid * CH;
    int s = 0;
    for (int i = 0; i < CH; i++) {
        int idx = base + i;
        if (idx < NN) s += d_degcur[idx];
    }
    part[tid] = s;
    __syncthreads();
    for (int off = 1; off < 1024; off <<= 1) {
        int v = (tid >= off) ? part[tid - off] : 0;
        __syncthreads();
        part[tid] += v;
        __syncthreads();
    }
    int run = (tid == 0) ? 0 : part[tid - 1];
    for (int i = 0; i < CH; i++) {
        int idx = base + i;
        if (idx < NN) {
            d_rowoff[idx] = run;
            int dr = d_degcur[idx];
            run += dr;
            float deg = (dr > 0) ? (float)dr : 1.0f;
            d_invdeg[idx] = 1.0f / deg;
            float logd = logf(deg + 1.0f);
            d_s1[idx] = logd / AVG_DEG_LOG;
            d_s2[idx] = AVG_DEG_LOG / logd;
        }
    }
    if (tid == 0) d_rowoff[NN] = part[1023];
}

__global__ void k_fillreorder(const int* __restrict__ ei, const float* __restrict__ eattr) {
    int e = blockIdx.x * blockDim.x + threadIdx.x;
    if (e >= EE) return;
    int dd = ei[EE + e];
    int pos = atomicAdd(&d_degcur[NN + dd], 1);
    int slot = d_rowoff[dd] + pos;
    d_src_s[slot] = ei[e];
    d_dst_s[slot] = dd;
    const float4* src = reinterpret_cast<const float4*>(eattr + (size_t)e * EDIM);
    float4* dst = reinterpret_cast<float4*>(d_eatt_s + (size_t)slot * EDIM);
#pragma unroll
    for (int j = 0; j < 4; j++) dst[j] = src[j];
}

// ---------------- once: compose C = W1e @ Ew, dv = W1e @ eb for ALL layers ----------------
__global__ void k_compose(const float* __restrict__ edge_w, const float* __restrict__ edge_b,
                          const float* __restrict__ pre_w1) {
    int l = blockIdx.x;
    int tid = threadIdx.x;
    const float* ew = edge_w + l * EDIM * FF;
    const float* ebias = edge_b + l * FF;
    const float* w1 = pre_w1 + l * TT * 3 * FF * FF;
    if (tid < TT * EDIM) {
        int t = tid / EDIM, k = tid % EDIM;
        float acc[FF];
#pragma unroll
        for (int o = 0; o < FF; o++) acc[o] = 0.f;
        for (int o = 0; o < FF; o++) {
            float ewv = tf32r(ew[k * FF + o]);
            const float* wrow = w1 + t * 3 * FF * FF + 2 * FF * FF + o * FF;
#pragma unroll
            for (int o2 = 0; o2 < FF; o2++) acc[o2] += ewv * tf32r(wrow[o2]);
        }
#pragma unroll
        for (int o2 = 0; o2 < FF; o2++)
            d_C[l * TT * EDIM * FF + t * EDIM * FF + k * FF + o2] = acc[o2];
    }
    if (tid < TT * FF) {
        int t = tid / FF, o2 = tid % FF;
        float a = 0.f;
        for (int o = 0; o < FF; o++)
            a += ebias[o] * tf32r(w1[t * 3 * FF * FF + 2 * FF * FF + o * FF + o2]);
        d_dv[l * TT * FF + tid] = a;
    }
}

// ---------------- node precompute: A = W1d@h, B = W1s@h ----------------
__global__ void __launch_bounds__(256) k_nodepre(const float* __restrict__ w1) {
    __shared__ __align__(16) float sWd[TT * FF * FF];
    __shared__ __align__(16) float sWs[TT * FF * FF];
    int tid = threadIdx.x;
    for (int i = tid; i < TT * FF * FF; i += 256) {
        int t = i / (FF * FF), r = i % (FF * FF);
        sWd[i] = tf32r(w1[t * 3 * FF * FF + r]);
        sWs[i] = tf32r(w1[t * 3 * FF * FF + FF * FF + r]);
    }
    __syncthreads();
    int n = blockIdx.x * 256 + tid;
    if (n >= NN) return;
    const float4* ph = reinterpret_cast<const float4*>(d_h + n * DD);
    for (int t = 0; t < TT; t++) {
        u64 aA[10], aB[10];
#pragma unroll
        for (int i = 0; i < 10; i++) { aA[i] = 0ull; aB[i] = 0ull; }
#pragma unroll
        for (int i4 = 0; i4 < 5; i4++) {
            float4 v = ph[t * 5 + i4];
            u64 px = tf32p(v.x), py = tf32p(v.y), pz = tf32p(v.z), pw = tf32p(v.w);
            fma20p(aA, px, sWd + t * 400 + (i4 * 4 + 0) * FF);
            fma20p(aA, py, sWd + t * 400 + (i4 * 4 + 1) * FF);
            fma20p(aA, pz, sWd + t * 400 + (i4 * 4 + 2) * FF);
            fma20p(aA, pw, sWd + t * 400 + (i4 * 4 + 3) * FF);
            fma20p(aB, px, sWs + t * 400 + (i4 * 4 + 0) * FF);
            fma20p(aB, py, sWs + t * 400 + (i4 * 4 + 1) * FF);
            fma20p(aB, pz, sWs + t * 400 + (i4 * 4 + 2) * FF);
            fma20p(aB, pw, sWs + t * 400 + (i4 * 4 + 3) * FF);
        }
        float4* pa = reinterpret_cast<float4*>(d_A + n * DD + t * FF);
        float4* pb = reinterpret_cast<float4*>(d_B + n * DD + t * FF);
#pragma unroll
        for (int i = 0; i < 5; i++) {
            float l0, h0, l1, h1;
            unpk(l0, h0, aA[2 * i]);
            unpk(l1, h1, aA[2 * i + 1]);
            pa[i] = make_float4(l0, h0, l1, h1);
            unpk(l0, h0, aB[2 * i]);
            unpk(l1, h1, aB[2 * i + 1]);
            pb[i] = make_float4(l0, h0, l1, h1);
        }
    }
}

// ---------------- edge MLP (composed ea path + dual-edge weight sharing) ----------------
#define EDGE_SMEM_FLOATS (1280 + 1600 + 80 + 80 + 32 * 128)

__global__ void __launch_bounds__(128) k_edge(int layer,
                       const float* __restrict__ b1, const float* __restrict__ w2,
                       const float* __restrict__ b2) {
    extern __shared__ float sm[];
    float* sC   = sm;                  // 1280
    float* sW2  = sm + 1280;           // 1600
    float* sB1c = sm + 2880;           // 80
    float* sB2  = sm + 2960;           // 80
    float* sAT  = sm + 3040;           // [32][128]
    int tid = threadIdx.x;
    const float* Cl = d_C + layer * TT * EDIM * FF;
    const float* dvl = d_dv + layer * TT * FF;
    for (int i = tid; i < TT * EDIM * FF; i += 128) sC[i] = tf32r(Cl[i]);
    for (int i = tid; i < TT * FF * FF; i += 128) sW2[i] = tf32r(w2[i]);
    for (int i = tid; i < TT * FF; i += 128) { sB1c[i] = b1[i] + dvl[i]; sB2[i] = b2[i]; }
    __syncthreads();

    int e0 = blockIdx.x * 256 + tid;
    int e1 = e0 + 128;
    int s0 = d_src_s[e0], dd0 = d_dst_s[e0];
    int s1i = d_src_s[e1], dd1 = d_dst_s[e1];

    {
        const float4* r0 = reinterpret_cast<const float4*>(d_eatt_s + (size_t)e0 * EDIM);
        const float4* r1 = reinterpret_cast<const float4*>(d_eatt_s + (size_t)e1 * EDIM);
#pragma unroll
        for (int j4 = 0; j4 < 4; j4++) {
            float4 v0 = r0[j4], v1 = r1[j4];
            sAT[(j4 * 4 + 0) * 128 + tid] = tf32r(v0.x);
            sAT[(j4 * 4 + 1) * 128 + tid] = tf32r(v0.y);
            sAT[(j4 * 4 + 2) * 128 + tid] = tf32r(v0.z);
            sAT[(j4 * 4 + 3) * 128 + tid] = tf32r(v0.w);
            sAT[(EDIM + j4 * 4 + 0) * 128 + tid] = tf32r(v1.x);
            sAT[(EDIM + j4 * 4 + 1) * 128 + tid] = tf32r(v1.y);
            sAT[(EDIM + j4 * 4 + 2) * 128 + tid] = tf32r(v1.z);
            sAT[(EDIM + j4 * 4 + 3) * 128 + tid] = tf32r(v1.w);
        }
    }

    float* m0 = d_m + (size_t)e0 * DD;
    float* m1 = d_m + (size_t)e1 * DD;
    for (int t = 0; t < TT; t++) {
        u64 pe0[10], pe1[10];
#pragma unroll
        for (int i = 0; i < 10; i++) { pe0[i] = 0ull; pe1[i] = 0ull; }
#pragma unroll
        for (int k = 0; k < EDIM; k++) {
            u64 b0 = bcast2(sAT[k * 128 + tid]);
            u64 b1v = bcast2(sAT[(EDIM + k) * 128 + tid]);
            fma20p2(pe0, pe1, b0, b1v, sC + t * EDIM * FF + k * FF);
        }

        const float4* pa0 = reinterpret_cast<const float4*>(d_A + dd0 * DD + t * FF);
        const float4* pb0 = reinterpret_cast<const float4*>(d_B + s0 * DD + t * FF);
        const float4* pa1 = reinterpret_cast<const float4*>(d_A + dd1 * DD + t * FF);
        const float4* pb1 = reinterpret_cast<const float4*>(d_B + s1i * DD + t * FF);
        float hs0[FF], hs1[FF];
#pragma unroll
        for (int i = 0; i < 5; i++) {
            float4 av = pa0[i];
            float4 bv = pb0[i];
            float lo, hi;
            unpk(lo, hi, pe0[2 * i]);
            hs0[4 * i + 0] = tf32r(fmaxf(av.x + bv.x + lo + sB1c[t * FF + 4 * i + 0], 0.f));
            hs0[4 * i + 1] = tf32r(fmaxf(av.y + bv.y + hi + sB1c[t * FF + 4 * i + 1], 0.f));
            unpk(lo, hi, pe0[2 * i + 1]);
            hs0[4 * i + 2] = tf32r(fmaxf(av.z + bv.z + lo + sB1c[t * FF + 4 * i + 2], 0.f));
            hs0[4 * i + 3] = tf32r(fmaxf(av.w + bv.w + hi + sB1c[t * FF + 4 * i + 3], 0.f));
        }
#pragma unroll
        for (int i = 0; i < 5; i++) {
            float4 av = pa1[i];
            float4 bv = pb1[i];
            float lo, hi;
            unpk(lo, hi, pe1[2 * i]);
            hs1[4 * i + 0] = tf32r(fmaxf(av.x + bv.x + lo + sB1c[t * FF + 4 * i + 0], 0.f));
            hs1[4 * i + 1] = tf32r(fmaxf(av.y + bv.y + hi + sB1c[t * FF + 4 * i + 1], 0.f));
            unpk(lo, hi, pe1[2 * i + 1]);
            hs1[4 * i + 2] = tf32r(fmaxf(av.z + bv.z + lo + sB1c[t * FF + 4 * i + 2], 0.f));
            hs1[4 * i + 3] = tf32r(fmaxf(av.w + bv.w + hi + sB1c[t * FF + 4 * i + 3], 0.f));
        }

        u64 o0[10], o1[10];
#pragma unroll
        for (int i = 0; i < 10; i++) { o0[i] = 0ull; o1[i] = 0ull; }
#pragma unroll
        for (int i = 0; i < FF; i++)
            fma20p2(o0, o1, bcast2(hs0[i]), bcast2(hs1[i]), sW2 + t * 400 + i * FF);
#pragma unroll
        for (int i = 0; i < 5; i++) {
            float l0, g0, l1, g1;
            unpk(l0, g0, o0[2 * i]);
            unpk(l1, g1, o0[2 * i + 1]);
            __stcs(reinterpret_cast<float4*>(m0 + t * FF) + i,
                   make_float4(l0 + sB2[t * FF + 4 * i], g0 + sB2[t * FF + 4 * i + 1],
                               l1 + sB2[t * FF + 4 * i + 2], g1 + sB2[t * FF + 4 * i + 3]));
            unpk(l0, g0, o1[2 * i]);
            unpk(l1, g1, o1[2 * i + 1]);
            __stcs(reinterpret_cast<float4*>(m1 + t * FF) + i,
                   make_float4(l0 + sB2[t * FF + 4 * i], g0 + sB2[t * FF + 4 * i + 1],
                               l1 + sB2[t * FF + 4 * i + 2], g1 + sB2[t * FF + 4 * i + 3]));
        }
    }
}

// ---------------- aggregation ----------------
__device__ __forceinline__ void agg_write(float* base, int d, float s, float q,
                                          float mn, float mx, float inv, bool he) {
    float mean = s * inv;
    float msq = q * inv;
    float sd = sqrtf(fmaxf(msq - mean * mean, 0.f) + EPS_STD);
    base[0 * DD + d] = mean;
    base[1 * DD + d] = he ? mn : 0.f;
    base[2 * DD + d] = he ? mx : 0.f;
    base[3 * DD + d] = sd;
}

__global__ void k_agg() {
    int warp = (blockIdx.x * blockDim.x + threadIdx.x) >> 5;
    int lane = threadIdx.x & 31;
    if (warp >= NN) return;
    int n = warp;
    int beg = d_rowoff[n], end = d_rowoff[n + 1];
    float s0 = 0, s1 = 0, s2 = 0, q0 = 0, q1 = 0, q2 = 0;
    float mn0 = INFINITY, mn1 = INFINITY, mn2 = INFINITY;
    float mx0 = -INFINITY, mx1 = -INFINITY, mx2 = -INFINITY;
    int i = beg;
    for (; i + 1 < end; i += 2) {
        const float* r0 = d_m + (size_t)i * DD;
        const float* r1 = r0 + DD;
        float a0 = __ldcs(r0 + lane);
        float a1 = __ldcs(r0 + 32 + lane);
        float b0 = __ldcs(r1 + lane);
        float b1 = __ldcs(r1 + 32 + lane);
        float a2 = 0.f, b2 = 0.f;
        if (lane < 16) { a2 = __ldcs(r0 + 64 + lane); b2 = __ldcs(r1 + 64 + lane); }
        s0 += a0; q0 += a0 * a0; mn0 = fminf(mn0, a0); mx0 = fmaxf(mx0, a0);
        s1 += a1; q1 += a1 * a1; mn1 = fminf(mn1, a1); mx1 = fmaxf(mx1, a1);
        s0 += b0; q0 += b0 * b0; mn0 = fminf(mn0, b0); mx0 = fmaxf(mx0, b0);
        s1 += b1; q1 += b1 * b1; mn1 = fminf(mn1, b1); mx1 = fmaxf(mx1, b1);
        if (lane < 16) {
            s2 += a2; q2 += a2 * a2; mn2 = fminf(mn2, a2); mx2 = fmaxf(mx2, a2);
            s2 += b2; q2 += b2 * b2; mn2 = fminf(mn2, b2); mx2 = fmaxf(mx2, b2);
        }
    }
    if (i < end) {
        const float* r0 = d_m + (size_t)i * DD;
        float a0 = __ldcs(r0 + lane);
        float a1 = __ldcs(r0 + 32 + lane);
        s0 += a0; q0 += a0 * a0; mn0 = fminf(mn0, a0); mx0 = fmaxf(mx0, a0);
        s1 += a1; q1 += a1 * a1; mn1 = fminf(mn1, a1); mx1 = fmaxf(mx1, a1);
        if (lane < 16) {
            float a2 = __ldcs(r0 + 64 + lane);
            s2 += a2; q2 += a2 * a2; mn2 = fminf(mn2, a2); mx2 = fmaxf(mx2, a2);
        }
    }
    float inv = d_invdeg[n];
    bool he = (end > beg);
    float* base = d_agg + n * 4 * DD;
    agg_write(base, lane, s0, q0, mn0, mx0, inv, he);
    agg_write(base, 32 + lane, s1, q1, mn1, mx1, inv, he);
    if (lane < 16) agg_write(base, 64 + lane, s2, q2, mn2, mx2, inv, he);
}

// ---------------- post MLP (tower-split) ----------------
__global__ void __launch_bounds__(256) k_post(const float* __restrict__ w1,
                                              const float* __restrict__ b1,
                                              const float* __restrict__ w2,
                                              const float* __restrict__ b2) {
    __shared__ __align__(16) float sW1[13 * FF * FF];
    __shared__ __align__(16) float sW2[FF * FF];
    __shared__ float sB1[FF];
    __shared__ float sB2[FF];
    int tid = threadIdx.x;
    int t = blockIdx.y;
    const float* w1t = w1 + t * 13 * FF * FF;
    const float* w2t = w2 + t * FF * FF;
    for (int i = tid; i < 13 * FF * FF; i += 256) sW1[i] = tf32r(w1t[i]);
    for (int i = tid; i < FF * FF; i += 256) sW2[i] = tf32r(w2t[i]);
    if (tid < FF) { sB1[tid] = b1[t * FF + tid]; sB2[tid] = b2[t * FF + tid]; }
    __syncthreads();

    int n = blockIdx.x * 256 + tid;
    if (n >= NN) return;
    float s1v = d_s1[n], s2v = d_s2[n];

    u64 hid[10];
#pragma unroll
    for (int i = 0; i < 10; i++) hid[i] = 0ull;
    const float4* px = reinterpret_cast<const float4*>(d_h + n * DD + t * FF);
#pragma unroll
    for (int i4 = 0; i4 < 5; i4++) {
        float4 v = px[i4];
        fma20p(hid, tf32p(v.x), sW1 + (i4 * 4 + 0) * FF);
        fma20p(hid, tf32p(v.y), sW1 + (i4 * 4 + 1) * FF);
        fma20p(hid, tf32p(v.z), sW1 + (i4 * 4 + 2) * FF);
        fma20p(hid, tf32p(v.w), sW1 + (i4 * 4 + 3) * FF);
    }
    for (int k = 0; k < 4; k++) {
        const float4* pa = reinterpret_cast<const float4*>(d_agg + n * 4 * DD + k * DD + t * FF);
#pragma unroll
        for (int f4 = 0; f4 < 5; f4++) {
            float4 v = pa[f4];
#pragma unroll
            for (int c = 0; c < 4; c++) {
                float a = (c == 0) ? v.x : (c == 1) ? v.y : (c == 2) ? v.z : v.w;
                int j = k * FF + f4 * 4 + c;
                fma20p(hid, tf32p(a), sW1 + (FF + j) * FF);
                fma20p(hid, tf32p(a * s1v), sW1 + (5 * FF + j) * FF);
                fma20p(hid, tf32p(a * s2v), sW1 + (9 * FF + j) * FF);
            }
        }
    }
    float hs[FF];
#pragma unroll
    for (int i = 0; i < 10; i++) {
        float lo, hi;
        unpk(lo, hi, hid[i]);
        hs[2 * i]     = tf32r(fmaxf(lo + sB1[2 * i], 0.f));
        hs[2 * i + 1] = tf32r(fmaxf(hi + sB1[2 * i + 1], 0.f));
    }
    u64 ov[10];
#pragma unroll
    for (int i = 0; i < 10; i++) ov[i] = 0ull;
#pragma unroll
    for (int i = 0; i < FF; i++) fma20p(ov, bcast2(hs[i]), sW2 + i * FF);
    float4* po = reinterpret_cast<float4*>(d_pre + n * DD + t * FF);
#pragma unroll
    for (int i = 0; i < 5; i++) {
        float l0, h0, l1, h1;
        unpk(l0, h0, ov[2 * i]);
        unpk(l1, h1, ov[2 * i + 1]);
        po[i] = make_float4(l0 + sB2[4 * i], h0 + sB2[4 * i + 1],
                            l1 + sB2[4 * i + 2], h1 + sB2[4 * i + 3]);
    }
}

// ---------------- lin ----------------
__global__ void k_lin(const float* __restrict__ lw, const float* __restrict__ lb) {
    __shared__ __align__(16) float sW[DD * DD];
    __shared__ __align__(16) float sLb[DD];
    int tid = threadIdx.x, bd = blockDim.x;
    for (int i = tid; i < DD * DD; i += bd) sW[i] = tf32r(lw[i]);
    for (int i = tid; i < DD; i += bd) sLb[i] = lb[i];
    __syncthreads();
    int n = blockIdx.x * bd + tid;
    if (n >= NN) return;
    const float4* pr = reinterpret_cast<const float4*>(d_pre + n * DD);
    u64 acc[40];
#pragma unroll
    for (int i = 0; i < 40; i++) acc[i] = 0ull;
#pragma unroll
    for (int k4 = 0; k4 < 20; k4++) {
        float4 v = pr[k4];
#pragma unroll
        for (int c = 0; c < 4; c++) {
            float a = (c == 0) ? v.x : (c == 1) ? v.y : (c == 2) ? v.z : v.w;
            u64 ap = tf32p(a);
            const float* wrow = sW + (k4 * 4 + c) * DD;
            fma20p(acc,      ap, wrow);
            fma20p(acc + 10, ap, wrow + 20);
            fma20p(acc + 20, ap, wrow + 40);
            fma20p(acc + 30, ap, wrow + 60);
        }
    }
    float4* po = reinterpret_cast<float4*>(d_lin + n * DD);
#pragma unroll
    for (int i = 0; i < 20; i++) {
        float l0, h0, l1, h1;
        unpk(l0, h0, acc[2 * i]);
        unpk(l1, h1, acc[2 * i + 1]);
        po[i] = make_float4(l0 + sLb[4 * i], h0 + sLb[4 * i + 1],
                            l1 + sLb[4 * i + 2], h1 + sLb[4 * i + 3]);
    }
}

// ---------------- batch norm ----------------
__global__ void k_zero_bn() {
    int i = threadIdx.x;
    if (i < DD) { d_bnsum[i] = 0.f; d_bnsq[i] = 0.f; }
}

__global__ void k_bn_stats() {
    int gid = blockIdx.x * blockDim.x + threadIdx.x;
    int f = gid % DD;
    float s = 0.f, q = 0.f;
    for (int i = gid; i < NN * DD; i += 40960) {
        float v = d_lin[i];
        s += v;
        q += v * v;
    }
    atomicAdd(&d_bnsum[f], s);
    atomicAdd(&d_bnsq[f], q);
}

__global__ void k_bn_final(const float* __restrict__ g, const float* __restrict__ b) {
    int i = threadIdx.x;
    if (i >= DD) return;
    float mu = d_bnsum[i] / (float)NN;
    float var = fmaxf(d_bnsq[i] / (float)NN - mu * mu, 0.f);
    float sc = g[i] * rsqrtf(var + EPS_BN);
    d_scale[i] = sc;
    d_shift[i] = b[i] - mu * sc;
}

__global__ void k_bn_apply() {
    int i = blockIdx.x * blockDim.x + threadIdx.x;
    if (i >= NN * DD) return;
    int d = i % DD;
    float v = d_lin[i] * d_scale[d] + d_shift[d];
    d_h[i] = fmaxf(v, 0.f) + d_h[i];
}

// ---------------- readout ----------------
__global__ void k_zero_pool() {
    int i = blockIdx.x * blockDim.x + threadIdx.x;
    if (i < GG * DD) d_gsum[i] = 0.f;
    if (i < GG) d_gcnt[i] = 0.f;
}

__global__ void k_pool(const int* __restrict__ batch) {
    int i = blockIdx.x * blockDim.x + threadIdx.x;
    if (i >= NN * DD) return;
    int n = i / DD, d = i % DD;
    int b = batch[n];
    atomicAdd(&d_gsum[b * DD + d], d_h[i]);
    if (d == 0) atomicAdd(&d_gcnt[b], 1.f);
}

__global__ void k_mlp(const float* __restrict__ w1, const float* __restrict__ b1,
                      const float* __restrict__ w2, const float* __restrict__ b2,
                      const float* __restrict__ w3, const float* __restrict__ b3,
                      float* __restrict__ out) {
    __shared__ float sw1[DD * 40];
    __shared__ float sb1[40];
    __shared__ float sw2[40 * 20];
    __shared__ float sb2[20];
    __shared__ float sw3[20];
    __shared__ float sb3;
    int tid = threadIdx.x;
    for (int i = tid; i < DD * 40; i += blockDim.x) sw1[i] = tf32r(w1[i]);
    for (int i = tid; i < 40 * 20; i += blockDim.x) sw2[i] = tf32r(w2[i]);
    if (tid < 40) sb1[tid] = b1[tid];
    if (tid < 20) { sb2[tid] = b2[tid]; sw3[tid] = tf32r(w3[tid]); }
    if (tid == 0) sb3 = b3[0];
    __syncthreads();

    int g = tid;
    if (g >= GG) return;
    float inv = 1.0f / fmaxf(d_gcnt[g], 1.0f);
    float gin[DD];
#pragma unroll
    for (int i = 0; i < DD; i++) gin[i] = tf32r(d_gsum[g * DD + i] * inv);
    float h1[40];
#pragma unroll
    for (int o = 0; o < 40; o++) h1[o] = 0.f;
#pragma unroll
    for (int i = 0; i < DD; i++) {
        float v = gin[i];
#pragma unroll
        for (int o = 0; o < 40; o++) h1[o] += v * sw1[i * 40 + o];
    }
#pragma unroll
    for (int o = 0; o < 40; o++) h1[o] = tf32r(fmaxf(h1[o] + sb1[o], 0.f));
    float h2[20];
#pragma unroll
    for (int o = 0; o < 20; o++) h2[o] = 0.f;
#pragma unroll
    for (int i = 0; i < 40; i++) {
        float v = h1[i];
#pragma unroll
        for (int o = 0; o < 20; o++) h2[o] += v * sw2[i * 20 + o];
    }
    float acc = 0.f;
#pragma unroll
    for (int i = 0; i < 20; i++) acc += tf32r(fmaxf(h2[i] + sb2[i], 0.f)) * sw3[i];
    out[g] = acc + sb3;
}

// ---------------- host launcher ----------------
extern "C" void kernel_launch(void* const* d_in, const int* in_sizes, int n_in,
                              void* d_out, int out_size) {
    (void)in_sizes; (void)n_in; (void)out_size;
    const int* x          = (const int*)d_in[0];
    const int* ei         = (const int*)d_in[1];
    const int* batch      = (const int*)d_in[2];
    const float* eattr    = (const float*)d_in[3];
    const float* aemb     = (const float*)d_in[4];
    const float* edge_w   = (const float*)d_in[5];
    const float* edge_b   = (const float*)d_in[6];
    const float* pre_w1   = (const float*)d_in[7];
    const float* pre_b1   = (const float*)d_in[8];
    const float* pre_w2   = (const float*)d_in[9];
    const float* pre_b2   = (const float*)d_in[10];
    const float* post_w1  = (const float*)d_in[11];
    const float* post_b1  = (const float*)d_in[12];
    const float* post_w2  = (const float*)d_in[13];
    const float* post_b2  = (const float*)d_in[14];
    const float* lin_w    = (const float*)d_in[15];
    const float* lin_b    = (const float*)d_in[16];
    const float* bn_g     = (const float*)d_in[17];
    const float* bn_b     = (const float*)d_in[18];
    const float* mlp_w1   = (const float*)d_in[19];
    const float* mlp_b1   = (const float*)d_in[20];
    const float* mlp_w2   = (const float*)d_in[21];
    const float* mlp_b2   = (const float*)d_in[22];
    const float* mlp_w3   = (const float*)d_in[23];
    const float* mlp_b3   = (const float*)d_in[24];
    float* out = (float*)d_out;

    const int EDGE_SMEM = EDGE_SMEM_FLOATS * 4;   // ~28.3 KB
    cudaFuncSetAttribute(k_edge, cudaFuncAttributeMaxDynamicSharedMemorySize, EDGE_SMEM);

    void* p_degcur = nullptr;
    cudaGetSymbolAddress(&p_degcur, d_degcur);
    cudaMemsetAsync(p_degcur, 0, 2 * NN * sizeof(int), 0);

    k_compose<<<LL, 128>>>(edge_w, edge_b, pre_w1);   // all layers, once
    k_count_init<<<(NN * 20 + 255) / 256, 256>>>(ei, x, aemb);
    k_scan<<<1, 1024>>>();
    k_fillreorder<<<(EE + 255) / 256, 256>>>(ei, eattr);

    for (int l = 0; l < LL; l++) {
        k_nodepre<<<(NN + 255) / 256, 256>>>(pre_w1 + l * TT * 3 * FF * FF);
        k_edge<<<EE / 256, 128, EDGE_SMEM>>>(l,
            pre_b1 + l * TT * FF,
            pre_w2 + l * TT * FF * FF, pre_b2 + l * TT * FF);
        k_agg<<<(NN * 32 + 255) / 256, 256>>>();
        k_post<<<dim3((NN + 255) / 256, TT), 256>>>(
            post_w1 + l * TT * 13 * FF * FF, post_b1 + l * TT * FF,
            post_w2 + l * TT * FF * FF, post_b2 + l * TT * FF);
        k_lin<<<(NN + 255) / 256, 256>>>(lin_w + l * DD * DD, lin_b + l * DD);
        k_zero_bn<<<1, 128>>>();
        k_bn_stats<<<128, 320>>>();
        k_bn_final<<<1, 80>>>(bn_g + l * DD, bn_b + l * DD);
        k_bn_apply<<<(NN * DD + 255) / 256, 256>>>();
    }

    k_zero_pool<<<(GG * DD + 255) / 256, 256>>>();
    k_pool<<<(NN * DD + 255) / 256, 256>>>(batch);
    k_mlp<<<1, 128>>>(mlp_w1, mlp_b1, mlp_w2, mlp_b2, mlp_w3, mlp_b3, out);
}